// round 5
// baseline (speedup 1.0000x reference)
#include <cuda_runtime.h>

// out[b, j] = prod_{k<=j} cos(x[b,k]) * cos(params[k])
// Closed form of the circuit: product state after RX/RY layers; CNOT chain maps
// Z_j -> Z_0...Z_j (Heisenberg); single-qubit <Z> after RY(p)RX(x)|0> = cos(p)cos(x).

#define N_WIRES 10

__global__ __launch_bounds__(128) void _QuantumGate_65481071395894_kernel(
    const float* __restrict__ x,      // (B, 10)
    const float* __restrict__ params, // (10,)
    float* __restrict__ out,          // (B, 10)
    int B)
{
    int b = blockIdx.x * blockDim.x + threadIdx.x;
    if (b >= B) return;

    // params: 3 vector loads instead of 10 scalar (all L2-broadcast after wave start)
    float4 p0 = __ldg(reinterpret_cast<const float4*>(params));      // p[0..3]
    float4 p1 = __ldg(reinterpret_cast<const float4*>(params) + 1);  // p[4..7]
    float2 p2 = __ldg(reinterpret_cast<const float2*>(params) + 4);  // p[8..9]
    float pv[N_WIRES] = {p0.x, p0.y, p0.z, p0.w, p1.x, p1.y, p1.z, p1.w, p2.x, p2.y};

    // Row = 40 bytes, 8-byte aligned -> 5x LDG.64 back-to-back (MLP=5)
    const float2* xr = reinterpret_cast<const float2*>(x + (size_t)b * N_WIRES);
    float xv[N_WIRES];
#pragma unroll
    for (int i = 0; i < 5; i++) {
        float2 v = __ldg(xr + i);
        xv[2 * i]     = v.x;
        xv[2 * i + 1] = v.y;
    }

    // 20 independent MUFU cos, pairwise multiply
    float c[N_WIRES];
#pragma unroll
    for (int k = 0; k < N_WIRES; k++) c[k] = __cosf(xv[k]) * __cosf(pv[k]);

    // Sklansky log-depth inclusive prefix product (depth 4 instead of chain depth 10)
#pragma unroll
    for (int d = 1; d < N_WIRES; d <<= 1) {
        float t[N_WIRES];
#pragma unroll
        for (int k = 0; k < N_WIRES; k++)
            t[k] = (k >= d) ? c[k] * c[((k >> (31 - __clz(d))) << (31 - __clz(d))) - 1]
                            : c[k];
        // the expression above is awkward for the compiler; use simple Hillis-Steele:
#pragma unroll
        for (int k = 0; k < N_WIRES; k++) t[k] = (k >= d) ? c[k] * c[k - d] : c[k];
#pragma unroll
        for (int k = 0; k < N_WIRES; k++) c[k] = t[k];
    }

    float2* orow = reinterpret_cast<float2*>(out + (size_t)b * N_WIRES);
#pragma unroll
    for (int i = 0; i < 5; i++) {
        orow[i] = make_float2(c[2 * i], c[2 * i + 1]);
    }
}

extern "C" void kernel_launch(void* const* d_in, const int* in_sizes, int n_in,
                              void* d_out, int out_size) {
    const float* x      = (const float*)d_in[0];   // (16384, 10) float32
    const float* params = (const float*)d_in[1];   // (10,) float32
    float* out          = (float*)d_out;           // (16384, 10) float32

    int B = in_sizes[0] / N_WIRES;      // 16384
    // Single balanced wave: 128 blocks x 128 threads = 16384 threads exactly,
    // one block per SM (128 of 148 SMs), no second-wave serialization.
    int threads = 128;
    int blocks = (B + threads - 1) / threads;
    _QuantumGate_65481071395894_kernel<<<blocks, threads>>>(x, params, out, B);
}

// round 6
// speedup vs baseline: 1.0642x; 1.0642x over previous
#include <cuda_runtime.h>

// out[b, j] = prod_{k<=j} cos(x[b,k]) * cos(params[k])
// Closed form of the circuit: product state after RX/RY layers; CNOT chain maps
// Z_j -> Z_0...Z_j (Heisenberg); single-qubit <Z> after RY(p)RX(x)|0> = cos(p)cos(x).
//
// Each thread processes TWO adjacent rows (80 B, 16B-aligned) so all global
// traffic is LDG.128 / STG.128: 5 loads + 5 stores per thread instead of 10+10.

#define N_WIRES 10

__global__ __launch_bounds__(64) void _QuantumGate_65481071395894_kernel(
    const float* __restrict__ x,      // (B, 10)
    const float* __restrict__ params, // (10,)
    float* __restrict__ out,          // (B, 10)
    int B)
{
    int t = blockIdx.x * blockDim.x + threadIdx.x;   // pair index
    int b0 = t * 2;
    if (b0 >= B) return;

    // params: 3 vector loads (L2-broadcast), then per-wire cos
    float4 p0 = __ldg(reinterpret_cast<const float4*>(params));      // p[0..3]
    float4 p1 = __ldg(reinterpret_cast<const float4*>(params) + 1);  // p[4..7]
    float2 p2 = __ldg(reinterpret_cast<const float2*>(params) + 4);  // p[8..9]
    const float pv[N_WIRES] = {p0.x, p0.y, p0.z, p0.w,
                               p1.x, p1.y, p1.z, p1.w, p2.x, p2.y};
    float cp[N_WIRES];
#pragma unroll
    for (int k = 0; k < N_WIRES; k++) cp[k] = __cosf(pv[k]);

    // 2 rows = 80 bytes at offset 80*t -> 16B aligned -> 5x LDG.128 (MLP=5)
    const float4* xr = reinterpret_cast<const float4*>(x + (size_t)b0 * N_WIRES);
    float xv[2 * N_WIRES];
#pragma unroll
    for (int i = 0; i < 5; i++) {
        float4 v = __ldg(xr + i);
        xv[4 * i + 0] = v.x;
        xv[4 * i + 1] = v.y;
        xv[4 * i + 2] = v.z;
        xv[4 * i + 3] = v.w;
    }

    // 20 independent MUFU cos + pairwise scale by cos(p), then two serial
    // prefix-product chains (independent -> dual-issue through FMA pipe).
    float c[2 * N_WIRES];
#pragma unroll
    for (int k = 0; k < N_WIRES; k++) {
        c[k]           = __cosf(xv[k])           * cp[k];
        c[N_WIRES + k] = __cosf(xv[N_WIRES + k]) * cp[k];
    }

    float r0 = 1.0f, r1 = 1.0f;
    float o[2 * N_WIRES];
#pragma unroll
    for (int k = 0; k < N_WIRES; k++) {
        r0 *= c[k];           o[k]           = r0;
        r1 *= c[N_WIRES + k]; o[N_WIRES + k] = r1;
    }

    float4* orow = reinterpret_cast<float4*>(out + (size_t)b0 * N_WIRES);
#pragma unroll
    for (int i = 0; i < 5; i++) {
        orow[i] = make_float4(o[4 * i], o[4 * i + 1], o[4 * i + 2], o[4 * i + 3]);
    }
}

extern "C" void kernel_launch(void* const* d_in, const int* in_sizes, int n_in,
                              void* d_out, int out_size) {
    const float* x      = (const float*)d_in[0];   // (16384, 10) float32
    const float* params = (const float*)d_in[1];   // (10,) float32
    float* out          = (float*)d_out;           // (16384, 10) float32

    int B = in_sizes[0] / N_WIRES;      // 16384
    int pairs = B / 2;                  // 8192 threads, one per row-pair
    int threads = 64;
    int blocks = (pairs + threads - 1) / threads;   // 128 blocks
    _QuantumGate_65481071395894_kernel<<<blocks, threads>>>(x, params, out, B);
}